// round 13
// baseline (speedup 1.0000x reference)
#include <cuda_runtime.h>
#include <cuda_bf16.h>
#include <math.h>
#include <stdint.h>

// Problem constants
#define Tn   2048
#define Dn   2048
#define Hn   16
#define HDn  128
#define Ln   512
#define RDn  64
#define Kn   32
#define KSPLIT 8
#define SCALE_ATTN (0.07216878364870323f)  // 1/sqrt(192)

typedef __nv_bfloat16 bf16;

// ---------------------------------------------------------------------------
// Scratch (static device globals)
// ---------------------------------------------------------------------------
__device__ float g_q  [Tn * Dn];
__device__ float g_qr [Tn * Hn * RDn];
__device__ float g_k  [Tn * Dn];
__device__ float g_v  [Tn * Dn];
__device__ float g_kr [Tn * RDn];
__device__ float g_krp[KSPLIT * Tn * RDn];   // kr split-K partials

__device__ bf16 g_x_hi  [Tn * Dn],  g_x_lo  [Tn * Dn];
__device__ bf16 g_ql_hi [Tn * Ln],  g_ql_lo [Tn * Ln];
__device__ bf16 g_ckv_hi[Tn * Ln],  g_ckv_lo[Tn * Ln];
__device__ bf16 g_ao_hi [Tn * Dn],  g_ao_lo [Tn * Dn];

__device__ bf16 g_WqdT_hi [Ln * Dn],        g_WqdT_lo [Ln * Dn];
__device__ bf16 g_WkvdT_hi[Ln * Dn],        g_WkvdT_lo[Ln * Dn];
__device__ bf16 g_WquT_hi [Dn * Ln],        g_WquT_lo [Dn * Ln];
__device__ bf16 g_WqrT_hi [Hn * RDn * Ln],  g_WqrT_lo [Hn * RDn * Ln];
__device__ bf16 g_WkuT_hi [Dn * Ln],        g_WkuT_lo [Dn * Ln];
__device__ bf16 g_WvuT_hi [Dn * Ln],        g_WvuT_lo [Dn * Ln];
__device__ bf16 g_WkrT_hi [RDn * Dn],       g_WkrT_lo [RDn * Dn];
__device__ bf16 g_WoT_hi  [Dn * Dn],        g_WoT_lo  [Dn * Dn];

// ---------------------------------------------------------------------------
// Low-level helpers (plain sm_80-era PTX only — no 'a'-suffix features)
// ---------------------------------------------------------------------------
__device__ __forceinline__ uint32_t smem_u32_of(const void* p) {
    uint32_t a;
    asm("{ .reg .u64 t; cvta.to.shared.u64 t, %1; cvt.u32.u64 %0, t; }"
        : "=r"(a) : "l"(p));
    return a;
}

__device__ __forceinline__ void cp16(uint32_t saddr, const void* gptr) {
    asm volatile("cp.async.cg.shared.global [%0], [%1], 16;"
                 :: "r"(saddr), "l"(gptr));
}
#define CP_COMMIT() asm volatile("cp.async.commit_group;" ::: "memory")
#define CP_WAIT0()  asm volatile("cp.async.wait_group 0;" ::: "memory")

__device__ __forceinline__ void ldm_x4(uint32_t* r, uint32_t addr) {
    asm volatile("ldmatrix.sync.aligned.m8n8.x4.shared.b16 {%0,%1,%2,%3}, [%4];"
                 : "=r"(r[0]), "=r"(r[1]), "=r"(r[2]), "=r"(r[3]) : "r"(addr));
}

__device__ __forceinline__ void mma_bf16(float* d, const uint32_t* a, const uint32_t* b) {
    asm volatile("mma.sync.aligned.m16n8k16.row.col.f32.bf16.bf16.f32 "
                 "{%0,%1,%2,%3}, {%4,%5,%6,%7}, {%8,%9}, {%0,%1,%2,%3};"
                 : "+f"(d[0]), "+f"(d[1]), "+f"(d[2]), "+f"(d[3])
                 : "r"(a[0]), "r"(a[1]), "r"(a[2]), "r"(a[3]),
                   "r"(b[0]), "r"(b[1]));
}

// ---------------------------------------------------------------------------
// Core split-bf16 mma.sync GEMM tile, occupancy-2 variant:
//   tile 128 x 64, K-chunk 64 (bf16, 128B smem rows), 2-stage cp.async pipe,
//   256 threads (8 warps as 4m x 2n; warp tile 32x32).
// EPI: 0 = fp32 store; 1 = bf16 hi/lo split store.
// ---------------------------------------------------------------------------
#define NTt 64
#define ABYTES (128 * 128)
#define BBYTES (NTt * 128)
#define STAGEB (2 * ABYTES + 2 * BBYTES)   // 49152
#define SMEM_MM (2 * STAGEB)               // 98304

template<int EPI>
__device__ __forceinline__ void mm_core(
    const bf16* __restrict__ Ahi, const bf16* __restrict__ Alo,
    const bf16* __restrict__ Bhi, const bf16* __restrict__ Blo,
    float* __restrict__ C, bf16* __restrict__ Chi, bf16* __restrict__ Clo,
    int Kd, int Ntot, int m0, int n0, int kbase, int nch, uint8_t* smem)
{
    constexpr int MI = 2;
    constexpr int NI = 4;

    const uint32_t sm32 = smem_u32_of(smem);
    const int tid  = threadIdx.x;
    const int wid  = tid >> 5;
    const int lane = tid & 31;

    const int mwarp = (wid & 3) * 32;
    const int nwarp = (wid >> 2) * 32;

    const int lchunk = tid & 7;
    const int lrow   = tid >> 3;

    float acc[MI][NI][4];
#pragma unroll
    for (int i = 0; i < MI; i++)
#pragma unroll
        for (int j = 0; j < NI; j++)
#pragma unroll
            for (int r = 0; r < 4; r++) acc[i][j][r] = 0.f;

    auto load_chunk = [&](int c, int s) {
        const uint32_t base = sm32 + s * STAGEB;
        const size_t kofs = (size_t)kbase + (size_t)c * 64 + lchunk * 8;
#pragma unroll
        for (int r = 0; r < 128; r += 32) {
            const int row = lrow + r;
            const size_t go = (size_t)(m0 + row) * Kd + kofs;
            const uint32_t so = base + row * 128 + ((lchunk ^ (row & 7)) << 4);
            cp16(so,          Ahi + go);
            cp16(so + ABYTES, Alo + go);
        }
#pragma unroll
        for (int r = 0; r < NTt; r += 32) {
            const int row = lrow + r;
            const size_t go = (size_t)(n0 + row) * Kd + kofs;
            const uint32_t so = base + 2 * ABYTES + row * 128 + ((lchunk ^ (row & 7)) << 4);
            cp16(so,          Bhi + go);
            cp16(so + BBYTES, Blo + go);
        }
        CP_COMMIT();
    };

    auto compute_chunk = [&](int s) {
        const uint32_t aBase = sm32 + s * STAGEB;
        const uint32_t bBase = aBase + 2 * ABYTES;
#pragma unroll
        for (int ks = 0; ks < 4; ks++) {
            uint32_t aHi[MI][4], aLo[MI][4], bHi[NI][2], bLo[NI][2];
#pragma unroll
            for (int mi = 0; mi < MI; mi++) {
                const int row = mwarp + mi * 16 + (lane & 15);
                const int chunk = ks * 2 + (lane >> 4);
                const uint32_t off = row * 128 + ((chunk ^ (row & 7)) << 4);
                ldm_x4(aHi[mi], aBase + off);
                ldm_x4(aLo[mi], aBase + ABYTES + off);
            }
#pragma unroll
            for (int nj = 0; nj < NI / 2; nj++) {
                const int row = nwarp + nj * 16 + ((lane >> 4) << 3) + (lane & 7);
                const int chunk = ks * 2 + ((lane >> 3) & 1);
                const uint32_t off = row * 128 + ((chunk ^ (row & 7)) << 4);
                uint32_t r4[4];
                ldm_x4(r4, bBase + off);
                bHi[nj * 2][0] = r4[0]; bHi[nj * 2][1] = r4[1];
                bHi[nj * 2 + 1][0] = r4[2]; bHi[nj * 2 + 1][1] = r4[3];
                ldm_x4(r4, bBase + BBYTES + off);
                bLo[nj * 2][0] = r4[0]; bLo[nj * 2][1] = r4[1];
                bLo[nj * 2 + 1][0] = r4[2]; bLo[nj * 2 + 1][1] = r4[3];
            }
#pragma unroll
            for (int mi = 0; mi < MI; mi++)
#pragma unroll
                for (int ni = 0; ni < NI; ni++) {
                    mma_bf16(acc[mi][ni], aHi[mi], bHi[ni]);
                    mma_bf16(acc[mi][ni], aHi[mi], bLo[ni]);
                    mma_bf16(acc[mi][ni], aLo[mi], bHi[ni]);
                }
        }
    };

    // 2-stage pipeline (occ-2 gives cross-CTA overlap)
    load_chunk(0, 0);
    for (int c = 0; c < nch; c++) {
        CP_WAIT0();
        __syncthreads();
        if (c + 1 < nch) load_chunk(c + 1, (c + 1) & 1);
        compute_chunk(c & 1);
        __syncthreads();
    }

#pragma unroll
    for (int mi = 0; mi < MI; mi++)
#pragma unroll
        for (int ni = 0; ni < NI; ni++) {
            const int row = m0 + mwarp + mi * 16 + (lane >> 2);
            const int col = n0 + nwarp + ni * 8 + ((lane & 3) << 1);
            if (EPI == 1) {
                float f0 = acc[mi][ni][0], f1 = acc[mi][ni][1];
                float f2 = acc[mi][ni][2], f3 = acc[mi][ni][3];
                bf16 h0 = __float2bfloat16(f0), h1 = __float2bfloat16(f1);
                bf16 h2 = __float2bfloat16(f2), h3 = __float2bfloat16(f3);
                bf16 l0 = __float2bfloat16(f0 - __bfloat162float(h0));
                bf16 l1 = __float2bfloat16(f1 - __bfloat162float(h1));
                bf16 l2 = __float2bfloat16(f2 - __bfloat162float(h2));
                bf16 l3 = __float2bfloat16(f3 - __bfloat162float(h3));
                *reinterpret_cast<__nv_bfloat162*>(Chi + (size_t)row * Ntot + col) =
                    __halves2bfloat162(h0, h1);
                *reinterpret_cast<__nv_bfloat162*>(Clo + (size_t)row * Ntot + col) =
                    __halves2bfloat162(l0, l1);
                *reinterpret_cast<__nv_bfloat162*>(Chi + (size_t)(row + 8) * Ntot + col) =
                    __halves2bfloat162(h2, h3);
                *reinterpret_cast<__nv_bfloat162*>(Clo + (size_t)(row + 8) * Ntot + col) =
                    __halves2bfloat162(l2, l3);
            } else {
                *reinterpret_cast<float2*>(C + (size_t)row * Ntot + col) =
                    make_float2(acc[mi][ni][0], acc[mi][ni][1]);
                *reinterpret_cast<float2*>(C + (size_t)(row + 8) * Ntot + col) =
                    make_float2(acc[mi][ni][2], acc[mi][ni][3]);
            }
        }
}

// ---------------------------------------------------------------------------
// GEMM wrapper kernels (occ-2)
// ---------------------------------------------------------------------------
// Down-projections + kr split-K: ql (128) | ckv (128) | kr (128) = 384 CTAs
__global__ __launch_bounds__(256, 2)
void mm_down_kernel(const bf16* __restrict__ xhi, const bf16* __restrict__ xlo,
                    const bf16* __restrict__ Bqhi, const bf16* __restrict__ Bqlo,
                    const bf16* __restrict__ Bkhi, const bf16* __restrict__ Bklo,
                    const bf16* __restrict__ Brhi, const bf16* __restrict__ Brlo,
                    bf16* __restrict__ qlhi, bf16* __restrict__ qllo,
                    bf16* __restrict__ ckvhi, bf16* __restrict__ ckvlo,
                    float* __restrict__ krp)
{
    extern __shared__ __align__(1024) uint8_t smem[];
    const int bx = blockIdx.x;
    if (bx < 128) {
        mm_core<1>(xhi, xlo, Bqhi, Bqlo, nullptr, qlhi, qllo,
                   Dn, Ln, (bx >> 3) * 128, (bx & 7) * 64, 0, 32, smem);
    } else if (bx < 256) {
        const int b = bx - 128;
        mm_core<1>(xhi, xlo, Bkhi, Bklo, nullptr, ckvhi, ckvlo,
                   Dn, Ln, (b >> 3) * 128, (b & 7) * 64, 0, 32, smem);
    } else {
        const int b = bx - 256;
        const int mt = b & 15;
        const int ks = b >> 4;
        mm_core<0>(xhi, xlo, Brhi, Brlo, krp + (size_t)ks * Tn * RDn,
                   nullptr, nullptr,
                   Dn, RDn, mt * 128, 0, ks * (Dn / KSPLIT), (Dn / KSPLIT) / 64, smem);
    }
}

// Up-projections: q (512) | qr (256) | k (512) | v (512) = 1792 CTAs
__global__ __launch_bounds__(256, 2)
void mm_up_kernel(const bf16* __restrict__ qlhi, const bf16* __restrict__ qllo,
                  const bf16* __restrict__ ckvhi, const bf16* __restrict__ ckvlo,
                  const bf16* __restrict__ Wquhi, const bf16* __restrict__ Wqulo,
                  const bf16* __restrict__ Wqrhi, const bf16* __restrict__ Wqrlo,
                  const bf16* __restrict__ Wkuhi, const bf16* __restrict__ Wkulo,
                  const bf16* __restrict__ Wvuhi, const bf16* __restrict__ Wvulo,
                  float* __restrict__ q, float* __restrict__ qr,
                  float* __restrict__ k, float* __restrict__ v)
{
    extern __shared__ __align__(1024) uint8_t smem[];
    const int bx = blockIdx.x;
    if (bx < 512) {
        mm_core<0>(qlhi, qllo, Wquhi, Wqulo, q, nullptr, nullptr,
                   Ln, Dn, (bx >> 5) * 128, (bx & 31) * 64, 0, 8, smem);
    } else if (bx < 768) {
        const int b = bx - 512;
        mm_core<0>(qlhi, qllo, Wqrhi, Wqrlo, qr, nullptr, nullptr,
                   Ln, Hn * RDn, (b >> 4) * 128, (b & 15) * 64, 0, 8, smem);
    } else if (bx < 1280) {
        const int b = bx - 768;
        mm_core<0>(ckvhi, ckvlo, Wkuhi, Wkulo, k, nullptr, nullptr,
                   Ln, Dn, (b >> 5) * 128, (b & 31) * 64, 0, 8, smem);
    } else {
        const int b = bx - 1280;
        mm_core<0>(ckvhi, ckvlo, Wvuhi, Wvulo, v, nullptr, nullptr,
                   Ln, Dn, (b >> 5) * 128, (b & 31) * 64, 0, 8, smem);
    }
}

// output projection: 512 CTAs
__global__ __launch_bounds__(256, 2)
void mm_wo_kernel(const bf16* __restrict__ aohi, const bf16* __restrict__ aolo,
                  const bf16* __restrict__ Bhi, const bf16* __restrict__ Blo,
                  float* __restrict__ out)
{
    extern __shared__ __align__(1024) uint8_t smem[];
    const int bx = blockIdx.x;
    mm_core<0>(aohi, aolo, Bhi, Blo, out, nullptr, nullptr,
               Dn, Dn, (bx >> 5) * 128, (bx & 31) * 64, 0, 32, smem);
}

// ---------------------------------------------------------------------------
// Merged preprocessing: x split (vectorized) + 8 weight transpose-splits.
// ---------------------------------------------------------------------------
__device__ __forceinline__ void tsplit_tile(
    const float* __restrict__ W, bf16* __restrict__ hi, bf16* __restrict__ lo,
    int Kd, int N, int bx, int by)
{
    __shared__ float tile[32][33];
    const int n0 = bx * 32, k0 = by * 32;
    const int tx = threadIdx.x & 31;
    const int ty = threadIdx.x >> 5;
#pragma unroll
    for (int i = 0; i < 32; i += 8)
        tile[ty + i][tx] = W[(size_t)(k0 + ty + i) * N + n0 + tx];
    __syncthreads();
#pragma unroll
    for (int i = 0; i < 32; i += 8) {
        float f = tile[tx][ty + i];
        bf16 h = __float2bfloat16(f);
        size_t o = (size_t)(n0 + ty + i) * Kd + k0 + tx;
        hi[o] = h;
        lo[o] = __float2bfloat16(f - __bfloat162float(h));
    }
}

__global__ __launch_bounds__(256)
void prep_kernel(const float* __restrict__ x,
                 const float* __restrict__ Wqd,  const float* __restrict__ Wqu,
                 const float* __restrict__ Wqr,  const float* __restrict__ Wkvd,
                 const float* __restrict__ Wku,  const float* __restrict__ Wvu,
                 const float* __restrict__ Wkr,  const float* __restrict__ Wo,
                 bf16* __restrict__ xhi, bf16* __restrict__ xlo,
                 bf16* __restrict__ WqdThi,  bf16* __restrict__ WqdTlo,
                 bf16* __restrict__ WkvdThi, bf16* __restrict__ WkvdTlo,
                 bf16* __restrict__ WquThi,  bf16* __restrict__ WquTlo,
                 bf16* __restrict__ WqrThi,  bf16* __restrict__ WqrTlo,
                 bf16* __restrict__ WkuThi,  bf16* __restrict__ WkuTlo,
                 bf16* __restrict__ WvuThi,  bf16* __restrict__ WvuTlo,
                 bf16* __restrict__ WkrThi,  bf16* __restrict__ WkrTlo,
                 bf16* __restrict__ WoThi,   bf16* __restrict__ WoTlo)
{
    const int b = blockIdx.x;
    if (b < 2048) {
        const int base = b * 2048 + threadIdx.x * 4;
#pragma unroll
        for (int rep = 0; rep < 2; rep++) {
            const int i = base + rep * 1024;
            float4 f = *reinterpret_cast<const float4*>(x + i);
            bf16 h0 = __float2bfloat16(f.x), h1 = __float2bfloat16(f.y);
            bf16 h2 = __float2bfloat16(f.z), h3 = __float2bfloat16(f.w);
            __nv_bfloat162 hA = __halves2bfloat162(h0, h1);
            __nv_bfloat162 hB = __halves2bfloat162(h2, h3);
            __nv_bfloat162 lA = __halves2bfloat162(
                __float2bfloat16(f.x - __bfloat162float(h0)),
                __float2bfloat16(f.y - __bfloat162float(h1)));
            __nv_bfloat162 lB = __halves2bfloat162(
                __float2bfloat16(f.z - __bfloat162float(h2)),
                __float2bfloat16(f.w - __bfloat162float(h3)));
            *reinterpret_cast<__nv_bfloat162*>(xhi + i)     = hA;
            *reinterpret_cast<__nv_bfloat162*>(xhi + i + 2) = hB;
            *reinterpret_cast<__nv_bfloat162*>(xlo + i)     = lA;
            *reinterpret_cast<__nv_bfloat162*>(xlo + i + 2) = lB;
        }
        return;
    }
    int rb = b - 2048;
    if (rb < 1024)      { tsplit_tile(Wqd,  WqdThi,  WqdTlo,  Dn, Ln,      rb & 15, rb >> 4); return; }
    rb -= 1024;
    if (rb < 1024)      { tsplit_tile(Wkvd, WkvdThi, WkvdTlo, Dn, Ln,      rb & 15, rb >> 4); return; }
    rb -= 1024;
    if (rb < 1024)      { tsplit_tile(Wqu,  WquThi,  WquTlo,  Ln, Dn,      rb & 63, rb >> 6); return; }
    rb -= 1024;
    if (rb < 512)       { tsplit_tile(Wqr,  WqrThi,  WqrTlo,  Ln, Hn*RDn,  rb & 31, rb >> 5); return; }
    rb -= 512;
    if (rb < 1024)      { tsplit_tile(Wku,  WkuThi,  WkuTlo,  Ln, Dn,      rb & 63, rb >> 6); return; }
    rb -= 1024;
    if (rb < 1024)      { tsplit_tile(Wvu,  WvuThi,  WvuTlo,  Ln, Dn,      rb & 63, rb >> 6); return; }
    rb -= 1024;
    if (rb < 128)       { tsplit_tile(Wkr,  WkrThi,  WkrTlo,  Dn, RDn,     rb & 1,  rb >> 1); return; }
    rb -= 128;
    /* Wo: 4096 */      { tsplit_tile(Wo,   WoThi,   WoTlo,   Dn, Dn,      rb & 63, rb >> 6); }
}

// ---------------------------------------------------------------------------
// Merged RoPE: qr in-place + kr split-K reduce + rope
// ---------------------------------------------------------------------------
__global__ void rope_kernel(float* __restrict__ qr,
                            const float* __restrict__ krp,
                            float* __restrict__ kr)
{
    int i = blockIdx.x * blockDim.x + threadIdx.x;
    if (i < Tn * Hn * 32) {
        int r = i & 31;
        int h = (i >> 5) & (Hn - 1);
        int t = i >> 9;
        float f = powf(10000.0f, -(float)r / 32.0f);
        float ang = (float)t * f;
        float c = cosf(ang), s = sinf(ang);
        int base = t * (Hn * RDn) + h * RDn + r;
        float a = qr[base];
        float bv = qr[base + 32];
        qr[base]      = a * c - bv * s;
        qr[base + 32] = bv * c + a * s;
        return;
    }
    i -= Tn * Hn * 32;
    if (i >= Tn * 32) return;
    int r = i & 31;
    int t = i >> 5;
    float a = 0.f, bv = 0.f;
#pragma unroll
    for (int s = 0; s < KSPLIT; s++) {
        a  += krp[(size_t)s * Tn * RDn + t * RDn + r];
        bv += krp[(size_t)s * Tn * RDn + t * RDn + r + 32];
    }
    float f = powf(10000.0f, -(float)r / 32.0f);
    float ang = (float)t * f;
    float c = cosf(ang), sn = sinf(ang);
    kr[t * RDn + r]      = a * c - bv * sn;
    kr[t * RDn + r + 32] = bv * c + a * sn;
}

// ---------------------------------------------------------------------------
// Sparse top-k attention (cooperative gather), emits bf16 hi/lo ao.
// ---------------------------------------------------------------------------
__global__ void attn_kernel(const float* __restrict__ q,
                            const float* __restrict__ qr,
                            const float* __restrict__ kmat,
                            const float* __restrict__ vmat,
                            const float* __restrict__ kr,
                            const int*   __restrict__ topk,
                            bf16* __restrict__ aohi, bf16* __restrict__ aolo)
{
    const int warp = (blockIdx.x * blockDim.x + threadIdx.x) >> 5;
    const int lane = threadIdx.x & 31;
    if (warp >= Tn * Hn) return;
    const int t = warp >> 4;
    const int h = warp & (Hn - 1);

    const int idx = topk[t * Kn + lane];

    const float4 qv = *reinterpret_cast<const float4*>(
        q + (size_t)t * Dn + h * HDn + lane * 4);
    const float2 qrv = *reinterpret_cast<const float2*>(
        qr + (size_t)t * (Hn * RDn) + h * RDn + lane * 2);

    float s = 0.f;
#pragma unroll
    for (int j = 0; j < Kn; j++) {
        const int ij = __shfl_sync(0xFFFFFFFFu, idx, j);
        const float4 kv = *reinterpret_cast<const float4*>(
            kmat + (size_t)ij * Dn + h * HDn + lane * 4);
        const float2 krv = *reinterpret_cast<const float2*>(
            kr + (size_t)ij * RDn + lane * 2);
        float p = qv.x * kv.x + qv.y * kv.y + qv.z * kv.z + qv.w * kv.w
                + qrv.x * krv.x + qrv.y * krv.y;
#pragma unroll
        for (int o = 16; o; o >>= 1) p += __shfl_xor_sync(0xFFFFFFFFu, p, o);
        if (lane == j) s = p;
    }
    s *= SCALE_ATTN;

    float m = s;
#pragma unroll
    for (int o = 16; o; o >>= 1) m = fmaxf(m, __shfl_xor_sync(0xFFFFFFFFu, m, o));
    float e = expf(s - m);
    float sum = e;
#pragma unroll
    for (int o = 16; o; o >>= 1) sum += __shfl_xor_sync(0xFFFFFFFFu, sum, o);
    float w = e / sum;

    float acc0 = 0.f, acc1 = 0.f, acc2 = 0.f, acc3 = 0.f;
#pragma unroll
    for (int j = 0; j < Kn; j++) {
        float wj = __shfl_sync(0xFFFFFFFFu, w, j);
        int   ij = __shfl_sync(0xFFFFFFFFu, idx, j);
        const float* vp = vmat + (size_t)ij * Dn + h * HDn;
        acc0 = fmaf(wj, vp[lane],      acc0);
        acc1 = fmaf(wj, vp[lane + 32], acc1);
        acc2 = fmaf(wj, vp[lane + 64], acc2);
        acc3 = fmaf(wj, vp[lane + 96], acc3);
    }
    const size_t opofs = (size_t)t * Dn + h * HDn;
    {
        bf16 h0 = __float2bfloat16(acc0);
        bf16 h1 = __float2bfloat16(acc1);
        bf16 h2 = __float2bfloat16(acc2);
        bf16 h3 = __float2bfloat16(acc3);
        aohi[opofs + lane]      = h0;
        aohi[opofs + lane + 32] = h1;
        aohi[opofs + lane + 64] = h2;
        aohi[opofs + lane + 96] = h3;
        aolo[opofs + lane]      = __float2bfloat16(acc0 - __bfloat162float(h0));
        aolo[opofs + lane + 32] = __float2bfloat16(acc1 - __bfloat162float(h1));
        aolo[opofs + lane + 64] = __float2bfloat16(acc2 - __bfloat162float(h2));
        aolo[opofs + lane + 96] = __float2bfloat16(acc3 - __bfloat162float(h3));
    }
}

// ---------------------------------------------------------------------------
// Launcher
// ---------------------------------------------------------------------------
extern "C" void kernel_launch(void* const* d_in, const int* in_sizes, int n_in,
                              void* d_out, int out_size)
{
    const float* x    = (const float*)d_in[0];
    const float* Wqd  = (const float*)d_in[1];
    const float* Wqu  = (const float*)d_in[2];
    const float* Wqr  = (const float*)d_in[3];
    const float* Wkvd = (const float*)d_in[4];
    const float* Wku  = (const float*)d_in[5];
    const float* Wvu  = (const float*)d_in[6];
    const float* Wkr  = (const float*)d_in[7];
    const float* Wo   = (const float*)d_in[8];
    const int*   topk = (const int*)  d_in[9];
    float* out = (float*)d_out;

    float *q, *qr, *k, *v, *kr, *krp;
    cudaGetSymbolAddress((void**)&q,   g_q);
    cudaGetSymbolAddress((void**)&qr,  g_qr);
    cudaGetSymbolAddress((void**)&k,   g_k);
    cudaGetSymbolAddress((void**)&v,   g_v);
    cudaGetSymbolAddress((void**)&kr,  g_kr);
    cudaGetSymbolAddress((void**)&krp, g_krp);

    bf16 *x_hi, *x_lo, *ql_hi, *ql_lo, *ckv_hi, *ckv_lo, *ao_hi, *ao_lo;
    cudaGetSymbolAddress((void**)&x_hi,   g_x_hi);
    cudaGetSymbolAddress((void**)&x_lo,   g_x_lo);
    cudaGetSymbolAddress((void**)&ql_hi,  g_ql_hi);
    cudaGetSymbolAddress((void**)&ql_lo,  g_ql_lo);
    cudaGetSymbolAddress((void**)&ckv_hi, g_ckv_hi);
    cudaGetSymbolAddress((void**)&ckv_lo, g_ckv_lo);
    cudaGetSymbolAddress((void**)&ao_hi,  g_ao_hi);
    cudaGetSymbolAddress((void**)&ao_lo,  g_ao_lo);

    bf16 *WqdT_hi, *WqdT_lo, *WkvdT_hi, *WkvdT_lo, *WquT_hi, *WquT_lo,
         *WqrT_hi, *WqrT_lo, *WkuT_hi, *WkuT_lo, *WvuT_hi, *WvuT_lo,
         *WkrT_hi, *WkrT_lo, *WoT_hi, *WoT_lo;
    cudaGetSymbolAddress((void**)&WqdT_hi,  g_WqdT_hi);
    cudaGetSymbolAddress((void**)&WqdT_lo,  g_WqdT_lo);
    cudaGetSymbolAddress((void**)&WkvdT_hi, g_WkvdT_hi);
    cudaGetSymbolAddress((void**)&WkvdT_lo, g_WkvdT_lo);
    cudaGetSymbolAddress((void**)&WquT_hi,  g_WquT_hi);
    cudaGetSymbolAddress((void**)&WquT_lo,  g_WquT_lo);
    cudaGetSymbolAddress((void**)&WqrT_hi,  g_WqrT_hi);
    cudaGetSymbolAddress((void**)&WqrT_lo,  g_WqrT_lo);
    cudaGetSymbolAddress((void**)&WkuT_hi,  g_WkuT_hi);
    cudaGetSymbolAddress((void**)&WkuT_lo,  g_WkuT_lo);
    cudaGetSymbolAddress((void**)&WvuT_hi,  g_WvuT_hi);
    cudaGetSymbolAddress((void**)&WvuT_lo,  g_WvuT_lo);
    cudaGetSymbolAddress((void**)&WkrT_hi,  g_WkrT_hi);
    cudaGetSymbolAddress((void**)&WkrT_lo,  g_WkrT_lo);
    cudaGetSymbolAddress((void**)&WoT_hi,   g_WoT_hi);
    cudaGetSymbolAddress((void**)&WoT_lo,   g_WoT_lo);

    cudaFuncSetAttribute(mm_down_kernel, cudaFuncAttributeMaxDynamicSharedMemorySize, SMEM_MM);
    cudaFuncSetAttribute(mm_up_kernel,   cudaFuncAttributeMaxDynamicSharedMemorySize, SMEM_MM);
    cudaFuncSetAttribute(mm_wo_kernel,   cudaFuncAttributeMaxDynamicSharedMemorySize, SMEM_MM);

    // 1) merged preprocessing
    prep_kernel<<<11904, 256>>>(x, Wqd, Wqu, Wqr, Wkvd, Wku, Wvu, Wkr, Wo,
                                x_hi, x_lo,
                                WqdT_hi, WqdT_lo, WkvdT_hi, WkvdT_lo,
                                WquT_hi, WquT_lo, WqrT_hi, WqrT_lo,
                                WkuT_hi, WkuT_lo, WvuT_hi, WvuT_lo,
                                WkrT_hi, WkrT_lo, WoT_hi, WoT_lo);

    // 2) down-projections + kr partials (merged, 384 CTAs @ occ2)
    mm_down_kernel<<<384, 256, SMEM_MM>>>(x_hi, x_lo,
                                          WqdT_hi, WqdT_lo, WkvdT_hi, WkvdT_lo,
                                          WkrT_hi, WkrT_lo,
                                          ql_hi, ql_lo, ckv_hi, ckv_lo, krp);

    // 3) up-projections (merged: q, qr, k, v; 1792 CTAs @ occ2)
    mm_up_kernel<<<1792, 256, SMEM_MM>>>(ql_hi, ql_lo, ckv_hi, ckv_lo,
                                         WquT_hi, WquT_lo, WqrT_hi, WqrT_lo,
                                         WkuT_hi, WkuT_lo, WvuT_hi, WvuT_lo,
                                         q, qr, k, v);

    // 4) merged rope
    rope_kernel<<<(Tn * Hn * 32 + Tn * 32 + 255) / 256, 256>>>(qr, krp, kr);

    // 5) sparse attention
    attn_kernel<<<(Tn * Hn * 32 + 255) / 256, 256>>>(q, qr, k, v, kr, topk, ao_hi, ao_lo);

    // 6) output projection (512 CTAs @ occ2)
    mm_wo_kernel<<<512, 256, SMEM_MM>>>(ao_hi, ao_lo, WoT_hi, WoT_lo, out);
}

// round 14
// speedup vs baseline: 1.0010x; 1.0010x over previous
#include <cuda_runtime.h>
#include <cuda_bf16.h>
#include <math.h>
#include <stdint.h>

// Problem constants
#define Tn   2048
#define Dn   2048
#define Hn   16
#define HDn  128
#define Ln   512
#define RDn  64
#define Kn   32
#define KSPLIT 8
#define SCALE_ATTN (0.07216878364870323f)  // 1/sqrt(192)

typedef __nv_bfloat16 bf16;

// ---------------------------------------------------------------------------
// Scratch (static device globals)
// ---------------------------------------------------------------------------
__device__ float g_q  [Tn * Dn];
__device__ float g_qr [Tn * Hn * RDn];
__device__ float g_k  [Tn * Dn];
__device__ float g_v  [Tn * Dn];
__device__ float g_kr [Tn * RDn];
__device__ float g_krp[KSPLIT * Tn * RDn];   // kr split-K partials

__device__ bf16 g_x_hi  [Tn * Dn],  g_x_lo  [Tn * Dn];
__device__ bf16 g_ql_hi [Tn * Ln],  g_ql_lo [Tn * Ln];
__device__ bf16 g_ckv_hi[Tn * Ln],  g_ckv_lo[Tn * Ln];
__device__ bf16 g_ao_hi [Tn * Dn],  g_ao_lo [Tn * Dn];

__device__ bf16 g_WqdT_hi [Ln * Dn],        g_WqdT_lo [Ln * Dn];
__device__ bf16 g_WkvdT_hi[Ln * Dn],        g_WkvdT_lo[Ln * Dn];
__device__ bf16 g_WquT_hi [Dn * Ln],        g_WquT_lo [Dn * Ln];
__device__ bf16 g_WqrT_hi [Hn * RDn * Ln],  g_WqrT_lo [Hn * RDn * Ln];
__device__ bf16 g_WkuT_hi [Dn * Ln],        g_WkuT_lo [Dn * Ln];
__device__ bf16 g_WvuT_hi [Dn * Ln],        g_WvuT_lo [Dn * Ln];
__device__ bf16 g_WkrT_hi [RDn * Dn],       g_WkrT_lo [RDn * Dn];
__device__ bf16 g_WoT_hi  [Dn * Dn],        g_WoT_lo  [Dn * Dn];

// ---------------------------------------------------------------------------
// Low-level helpers (plain sm_80-era PTX only — no 'a'-suffix features)
// ---------------------------------------------------------------------------
__device__ __forceinline__ uint32_t smem_u32_of(const void* p) {
    uint32_t a;
    asm("{ .reg .u64 t; cvta.to.shared.u64 t, %1; cvt.u32.u64 %0, t; }"
        : "=r"(a) : "l"(p));
    return a;
}

__device__ __forceinline__ void cp16(uint32_t saddr, const void* gptr) {
    asm volatile("cp.async.cg.shared.global [%0], [%1], 16;"
                 :: "r"(saddr), "l"(gptr));
}
#define CP_COMMIT() asm volatile("cp.async.commit_group;" ::: "memory")
#define CP_WAIT0()  asm volatile("cp.async.wait_group 0;" ::: "memory")

__device__ __forceinline__ void ldm_x4(uint32_t* r, uint32_t addr) {
    asm volatile("ldmatrix.sync.aligned.m8n8.x4.shared.b16 {%0,%1,%2,%3}, [%4];"
                 : "=r"(r[0]), "=r"(r[1]), "=r"(r[2]), "=r"(r[3]) : "r"(addr));
}

__device__ __forceinline__ void mma_bf16(float* d, const uint32_t* a, const uint32_t* b) {
    asm volatile("mma.sync.aligned.m16n8k16.row.col.f32.bf16.bf16.f32 "
                 "{%0,%1,%2,%3}, {%4,%5,%6,%7}, {%8,%9}, {%0,%1,%2,%3};"
                 : "+f"(d[0]), "+f"(d[1]), "+f"(d[2]), "+f"(d[3])
                 : "r"(a[0]), "r"(a[1]), "r"(a[2]), "r"(a[3]),
                   "r"(b[0]), "r"(b[1]));
}

// ---------------------------------------------------------------------------
// Core split-bf16 mma.sync GEMM tile, occupancy-2 variant:
//   tile 128 x 64, K-chunk 64 (bf16, 128B smem rows), 2-stage cp.async pipe,
//   256 threads (8 warps as 4m x 2n; warp tile 32x32).
// EPI: 0 = fp32 store; 1 = bf16 hi/lo split store.
// ---------------------------------------------------------------------------
#define NTt 64
#define ABYTES (128 * 128)
#define BBYTES (NTt * 128)
#define STAGEB (2 * ABYTES + 2 * BBYTES)   // 49152
#define SMEM_MM (2 * STAGEB)               // 98304

template<int EPI>
__device__ __forceinline__ void mm_core(
    const bf16* __restrict__ Ahi, const bf16* __restrict__ Alo,
    const bf16* __restrict__ Bhi, const bf16* __restrict__ Blo,
    float* __restrict__ C, bf16* __restrict__ Chi, bf16* __restrict__ Clo,
    int Kd, int Ntot, int m0, int n0, int kbase, int nch, uint8_t* smem)
{
    constexpr int MI = 2;
    constexpr int NI = 4;

    const uint32_t sm32 = smem_u32_of(smem);
    const int tid  = threadIdx.x;
    const int wid  = tid >> 5;
    const int lane = tid & 31;

    const int mwarp = (wid & 3) * 32;
    const int nwarp = (wid >> 2) * 32;

    const int lchunk = tid & 7;
    const int lrow   = tid >> 3;

    float acc[MI][NI][4];
#pragma unroll
    for (int i = 0; i < MI; i++)
#pragma unroll
        for (int j = 0; j < NI; j++)
#pragma unroll
            for (int r = 0; r < 4; r++) acc[i][j][r] = 0.f;

    auto load_chunk = [&](int c, int s) {
        const uint32_t base = sm32 + s * STAGEB;
        const size_t kofs = (size_t)kbase + (size_t)c * 64 + lchunk * 8;
#pragma unroll
        for (int r = 0; r < 128; r += 32) {
            const int row = lrow + r;
            const size_t go = (size_t)(m0 + row) * Kd + kofs;
            const uint32_t so = base + row * 128 + ((lchunk ^ (row & 7)) << 4);
            cp16(so,          Ahi + go);
            cp16(so + ABYTES, Alo + go);
        }
#pragma unroll
        for (int r = 0; r < NTt; r += 32) {
            const int row = lrow + r;
            const size_t go = (size_t)(n0 + row) * Kd + kofs;
            const uint32_t so = base + 2 * ABYTES + row * 128 + ((lchunk ^ (row & 7)) << 4);
            cp16(so,          Bhi + go);
            cp16(so + BBYTES, Blo + go);
        }
        CP_COMMIT();
    };

    auto compute_chunk = [&](int s) {
        const uint32_t aBase = sm32 + s * STAGEB;
        const uint32_t bBase = aBase + 2 * ABYTES;
#pragma unroll
        for (int ks = 0; ks < 4; ks++) {
            uint32_t aHi[MI][4], aLo[MI][4], bHi[NI][2], bLo[NI][2];
#pragma unroll
            for (int mi = 0; mi < MI; mi++) {
                const int row = mwarp + mi * 16 + (lane & 15);
                const int chunk = ks * 2 + (lane >> 4);
                const uint32_t off = row * 128 + ((chunk ^ (row & 7)) << 4);
                ldm_x4(aHi[mi], aBase + off);
                ldm_x4(aLo[mi], aBase + ABYTES + off);
            }
#pragma unroll
            for (int nj = 0; nj < NI / 2; nj++) {
                const int row = nwarp + nj * 16 + ((lane >> 4) << 3) + (lane & 7);
                const int chunk = ks * 2 + ((lane >> 3) & 1);
                const uint32_t off = row * 128 + ((chunk ^ (row & 7)) << 4);
                uint32_t r4[4];
                ldm_x4(r4, bBase + off);
                bHi[nj * 2][0] = r4[0]; bHi[nj * 2][1] = r4[1];
                bHi[nj * 2 + 1][0] = r4[2]; bHi[nj * 2 + 1][1] = r4[3];
                ldm_x4(r4, bBase + BBYTES + off);
                bLo[nj * 2][0] = r4[0]; bLo[nj * 2][1] = r4[1];
                bLo[nj * 2 + 1][0] = r4[2]; bLo[nj * 2 + 1][1] = r4[3];
            }
#pragma unroll
            for (int mi = 0; mi < MI; mi++)
#pragma unroll
                for (int ni = 0; ni < NI; ni++) {
                    mma_bf16(acc[mi][ni], aHi[mi], bHi[ni]);
                    mma_bf16(acc[mi][ni], aHi[mi], bLo[ni]);
                    mma_bf16(acc[mi][ni], aLo[mi], bHi[ni]);
                }
        }
    };

    // 2-stage pipeline (occ-2 gives cross-CTA overlap)
    load_chunk(0, 0);
    for (int c = 0; c < nch; c++) {
        CP_WAIT0();
        __syncthreads();
        if (c + 1 < nch) load_chunk(c + 1, (c + 1) & 1);
        compute_chunk(c & 1);
        __syncthreads();
    }

#pragma unroll
    for (int mi = 0; mi < MI; mi++)
#pragma unroll
        for (int ni = 0; ni < NI; ni++) {
            const int row = m0 + mwarp + mi * 16 + (lane >> 2);
            const int col = n0 + nwarp + ni * 8 + ((lane & 3) << 1);
            if (EPI == 1) {
                float f0 = acc[mi][ni][0], f1 = acc[mi][ni][1];
                float f2 = acc[mi][ni][2], f3 = acc[mi][ni][3];
                bf16 h0 = __float2bfloat16(f0), h1 = __float2bfloat16(f1);
                bf16 h2 = __float2bfloat16(f2), h3 = __float2bfloat16(f3);
                bf16 l0 = __float2bfloat16(f0 - __bfloat162float(h0));
                bf16 l1 = __float2bfloat16(f1 - __bfloat162float(h1));
                bf16 l2 = __float2bfloat16(f2 - __bfloat162float(h2));
                bf16 l3 = __float2bfloat16(f3 - __bfloat162float(h3));
                *reinterpret_cast<__nv_bfloat162*>(Chi + (size_t)row * Ntot + col) =
                    __halves2bfloat162(h0, h1);
                *reinterpret_cast<__nv_bfloat162*>(Clo + (size_t)row * Ntot + col) =
                    __halves2bfloat162(l0, l1);
                *reinterpret_cast<__nv_bfloat162*>(Chi + (size_t)(row + 8) * Ntot + col) =
                    __halves2bfloat162(h2, h3);
                *reinterpret_cast<__nv_bfloat162*>(Clo + (size_t)(row + 8) * Ntot + col) =
                    __halves2bfloat162(l2, l3);
            } else {
                *reinterpret_cast<float2*>(C + (size_t)row * Ntot + col) =
                    make_float2(acc[mi][ni][0], acc[mi][ni][1]);
                *reinterpret_cast<float2*>(C + (size_t)(row + 8) * Ntot + col) =
                    make_float2(acc[mi][ni][2], acc[mi][ni][3]);
            }
        }
}

// ---------------------------------------------------------------------------
// GEMM wrapper kernels (occ-2)
// ---------------------------------------------------------------------------
// Down-projections + kr split-K: ql (128) | ckv (128) | kr (128) = 384 CTAs
__global__ __launch_bounds__(256, 2)
void mm_down_kernel(const bf16* __restrict__ xhi, const bf16* __restrict__ xlo,
                    const bf16* __restrict__ Bqhi, const bf16* __restrict__ Bqlo,
                    const bf16* __restrict__ Bkhi, const bf16* __restrict__ Bklo,
                    const bf16* __restrict__ Brhi, const bf16* __restrict__ Brlo,
                    bf16* __restrict__ qlhi, bf16* __restrict__ qllo,
                    bf16* __restrict__ ckvhi, bf16* __restrict__ ckvlo,
                    float* __restrict__ krp)
{
    extern __shared__ __align__(1024) uint8_t smem[];
    const int bx = blockIdx.x;
    if (bx < 128) {
        mm_core<1>(xhi, xlo, Bqhi, Bqlo, nullptr, qlhi, qllo,
                   Dn, Ln, (bx >> 3) * 128, (bx & 7) * 64, 0, 32, smem);
    } else if (bx < 256) {
        const int b = bx - 128;
        mm_core<1>(xhi, xlo, Bkhi, Bklo, nullptr, ckvhi, ckvlo,
                   Dn, Ln, (b >> 3) * 128, (b & 7) * 64, 0, 32, smem);
    } else {
        const int b = bx - 256;
        const int mt = b & 15;
        const int ks = b >> 4;
        mm_core<0>(xhi, xlo, Brhi, Brlo, krp + (size_t)ks * Tn * RDn,
                   nullptr, nullptr,
                   Dn, RDn, mt * 128, 0, ks * (Dn / KSPLIT), (Dn / KSPLIT) / 64, smem);
    }
}

// Up-projections: q (512) | qr (256) | k (512) | v (512) = 1792 CTAs
__global__ __launch_bounds__(256, 2)
void mm_up_kernel(const bf16* __restrict__ qlhi, const bf16* __restrict__ qllo,
                  const bf16* __restrict__ ckvhi, const bf16* __restrict__ ckvlo,
                  const bf16* __restrict__ Wquhi, const bf16* __restrict__ Wqulo,
                  const bf16* __restrict__ Wqrhi, const bf16* __restrict__ Wqrlo,
                  const bf16* __restrict__ Wkuhi, const bf16* __restrict__ Wkulo,
                  const bf16* __restrict__ Wvuhi, const bf16* __restrict__ Wvulo,
                  float* __restrict__ q, float* __restrict__ qr,
                  float* __restrict__ k, float* __restrict__ v)
{
    extern __shared__ __align__(1024) uint8_t smem[];
    const int bx = blockIdx.x;
    if (bx < 512) {
        mm_core<0>(qlhi, qllo, Wquhi, Wqulo, q, nullptr, nullptr,
                   Ln, Dn, (bx >> 5) * 128, (bx & 31) * 64, 0, 8, smem);
    } else if (bx < 768) {
        const int b = bx - 512;
        mm_core<0>(qlhi, qllo, Wqrhi, Wqrlo, qr, nullptr, nullptr,
                   Ln, Hn * RDn, (b >> 4) * 128, (b & 15) * 64, 0, 8, smem);
    } else if (bx < 1280) {
        const int b = bx - 768;
        mm_core<0>(ckvhi, ckvlo, Wkuhi, Wkulo, k, nullptr, nullptr,
                   Ln, Dn, (b >> 5) * 128, (b & 31) * 64, 0, 8, smem);
    } else {
        const int b = bx - 1280;
        mm_core<0>(ckvhi, ckvlo, Wvuhi, Wvulo, v, nullptr, nullptr,
                   Ln, Dn, (b >> 5) * 128, (b & 31) * 64, 0, 8, smem);
    }
}

// output projection: 512 CTAs
__global__ __launch_bounds__(256, 2)
void mm_wo_kernel(const bf16* __restrict__ aohi, const bf16* __restrict__ aolo,
                  const bf16* __restrict__ Bhi, const bf16* __restrict__ Blo,
                  float* __restrict__ out)
{
    extern __shared__ __align__(1024) uint8_t smem[];
    const int bx = blockIdx.x;
    mm_core<0>(aohi, aolo, Bhi, Blo, out, nullptr, nullptr,
               Dn, Dn, (bx >> 5) * 128, (bx & 31) * 64, 0, 32, smem);
}

// ---------------------------------------------------------------------------
// Merged preprocessing: x split (vectorized) + 8 weight transpose-splits.
// ---------------------------------------------------------------------------
__device__ __forceinline__ void tsplit_tile(
    const float* __restrict__ W, bf16* __restrict__ hi, bf16* __restrict__ lo,
    int Kd, int N, int bx, int by)
{
    __shared__ float tile[32][33];
    const int n0 = bx * 32, k0 = by * 32;
    const int tx = threadIdx.x & 31;
    const int ty = threadIdx.x >> 5;
#pragma unroll
    for (int i = 0; i < 32; i += 8)
        tile[ty + i][tx] = W[(size_t)(k0 + ty + i) * N + n0 + tx];
    __syncthreads();
#pragma unroll
    for (int i = 0; i < 32; i += 8) {
        float f = tile[tx][ty + i];
        bf16 h = __float2bfloat16(f);
        size_t o = (size_t)(n0 + ty + i) * Kd + k0 + tx;
        hi[o] = h;
        lo[o] = __float2bfloat16(f - __bfloat162float(h));
    }
}

__global__ __launch_bounds__(256)
void prep_kernel(const float* __restrict__ x,
                 const float* __restrict__ Wqd,  const float* __restrict__ Wqu,
                 const float* __restrict__ Wqr,  const float* __restrict__ Wkvd,
                 const float* __restrict__ Wku,  const float* __restrict__ Wvu,
                 const float* __restrict__ Wkr,  const float* __restrict__ Wo,
                 bf16* __restrict__ xhi, bf16* __restrict__ xlo,
                 bf16* __restrict__ WqdThi,  bf16* __restrict__ WqdTlo,
                 bf16* __restrict__ WkvdThi, bf16* __restrict__ WkvdTlo,
                 bf16* __restrict__ WquThi,  bf16* __restrict__ WquTlo,
                 bf16* __restrict__ WqrThi,  bf16* __restrict__ WqrTlo,
                 bf16* __restrict__ WkuThi,  bf16* __restrict__ WkuTlo,
                 bf16* __restrict__ WvuThi,  bf16* __restrict__ WvuTlo,
                 bf16* __restrict__ WkrThi,  bf16* __restrict__ WkrTlo,
                 bf16* __restrict__ WoThi,   bf16* __restrict__ WoTlo)
{
    const int b = blockIdx.x;
    if (b < 2048) {
        const int base = b * 2048 + threadIdx.x * 4;
#pragma unroll
        for (int rep = 0; rep < 2; rep++) {
            const int i = base + rep * 1024;
            float4 f = *reinterpret_cast<const float4*>(x + i);
            bf16 h0 = __float2bfloat16(f.x), h1 = __float2bfloat16(f.y);
            bf16 h2 = __float2bfloat16(f.z), h3 = __float2bfloat16(f.w);
            __nv_bfloat162 hA = __halves2bfloat162(h0, h1);
            __nv_bfloat162 hB = __halves2bfloat162(h2, h3);
            __nv_bfloat162 lA = __halves2bfloat162(
                __float2bfloat16(f.x - __bfloat162float(h0)),
                __float2bfloat16(f.y - __bfloat162float(h1)));
            __nv_bfloat162 lB = __halves2bfloat162(
                __float2bfloat16(f.z - __bfloat162float(h2)),
                __float2bfloat16(f.w - __bfloat162float(h3)));
            *reinterpret_cast<__nv_bfloat162*>(xhi + i)     = hA;
            *reinterpret_cast<__nv_bfloat162*>(xhi + i + 2) = hB;
            *reinterpret_cast<__nv_bfloat162*>(xlo + i)     = lA;
            *reinterpret_cast<__nv_bfloat162*>(xlo + i + 2) = lB;
        }
        return;
    }
    int rb = b - 2048;
    if (rb < 1024)      { tsplit_tile(Wqd,  WqdThi,  WqdTlo,  Dn, Ln,      rb & 15, rb >> 4); return; }
    rb -= 1024;
    if (rb < 1024)      { tsplit_tile(Wkvd, WkvdThi, WkvdTlo, Dn, Ln,      rb & 15, rb >> 4); return; }
    rb -= 1024;
    if (rb < 1024)      { tsplit_tile(Wqu,  WquThi,  WquTlo,  Ln, Dn,      rb & 63, rb >> 6); return; }
    rb -= 1024;
    if (rb < 512)       { tsplit_tile(Wqr,  WqrThi,  WqrTlo,  Ln, Hn*RDn,  rb & 31, rb >> 5); return; }
    rb -= 512;
    if (rb < 1024)      { tsplit_tile(Wku,  WkuThi,  WkuTlo,  Ln, Dn,      rb & 63, rb >> 6); return; }
    rb -= 1024;
    if (rb < 1024)      { tsplit_tile(Wvu,  WvuThi,  WvuTlo,  Ln, Dn,      rb & 63, rb >> 6); return; }
    rb -= 1024;
    if (rb < 128)       { tsplit_tile(Wkr,  WkrThi,  WkrTlo,  Dn, RDn,     rb & 1,  rb >> 1); return; }
    rb -= 128;
    /* Wo: 4096 */      { tsplit_tile(Wo,   WoThi,   WoTlo,   Dn, Dn,      rb & 63, rb >> 6); }
}

// ---------------------------------------------------------------------------
// Merged RoPE: qr in-place + kr split-K reduce + rope
// ---------------------------------------------------------------------------
__global__ void rope_kernel(float* __restrict__ qr,
                            const float* __restrict__ krp,
                            float* __restrict__ kr)
{
    int i = blockIdx.x * blockDim.x + threadIdx.x;
    if (i < Tn * Hn * 32) {
        int r = i & 31;
        int h = (i >> 5) & (Hn - 1);
        int t = i >> 9;
        float f = powf(10000.0f, -(float)r / 32.0f);
        float ang = (float)t * f;
        float c = cosf(ang), s = sinf(ang);
        int base = t * (Hn * RDn) + h * RDn + r;
        float a = qr[base];
        float bv = qr[base + 32];
        qr[base]      = a * c - bv * s;
        qr[base + 32] = bv * c + a * s;
        return;
    }
    i -= Tn * Hn * 32;
    if (i >= Tn * 32) return;
    int r = i & 31;
    int t = i >> 5;
    float a = 0.f, bv = 0.f;
#pragma unroll
    for (int s = 0; s < KSPLIT; s++) {
        a  += krp[(size_t)s * Tn * RDn + t * RDn + r];
        bv += krp[(size_t)s * Tn * RDn + t * RDn + r + 32];
    }
    float f = powf(10000.0f, -(float)r / 32.0f);
    float ang = (float)t * f;
    float c = cosf(ang), sn = sinf(ang);
    kr[t * RDn + r]      = a * c - bv * sn;
    kr[t * RDn + r + 32] = bv * c + a * sn;
}

// ---------------------------------------------------------------------------
// Sparse top-k attention (cooperative gather), emits bf16 hi/lo ao.
// ---------------------------------------------------------------------------
__global__ void attn_kernel(const float* __restrict__ q,
                            const float* __restrict__ qr,
                            const float* __restrict__ kmat,
                            const float* __restrict__ vmat,
                            const float* __restrict__ kr,
                            const int*   __restrict__ topk,
                            bf16* __restrict__ aohi, bf16* __restrict__ aolo)
{
    const int warp = (blockIdx.x * blockDim.x + threadIdx.x) >> 5;
    const int lane = threadIdx.x & 31;
    if (warp >= Tn * Hn) return;
    const int t = warp >> 4;
    const int h = warp & (Hn - 1);

    const int idx = topk[t * Kn + lane];

    const float4 qv = *reinterpret_cast<const float4*>(
        q + (size_t)t * Dn + h * HDn + lane * 4);
    const float2 qrv = *reinterpret_cast<const float2*>(
        qr + (size_t)t * (Hn * RDn) + h * RDn + lane * 2);

    float s = 0.f;
#pragma unroll
    for (int j = 0; j < Kn; j++) {
        const int ij = __shfl_sync(0xFFFFFFFFu, idx, j);
        const float4 kv = *reinterpret_cast<const float4*>(
            kmat + (size_t)ij * Dn + h * HDn + lane * 4);
        const float2 krv = *reinterpret_cast<const float2*>(
            kr + (size_t)ij * RDn + lane * 2);
        float p = qv.x * kv.x + qv.y * kv.y + qv.z * kv.z + qv.w * kv.w
                + qrv.x * krv.x + qrv.y * krv.y;
#pragma unroll
        for (int o = 16; o; o >>= 1) p += __shfl_xor_sync(0xFFFFFFFFu, p, o);
        if (lane == j) s = p;
    }
    s *= SCALE_ATTN;

    float m = s;
#pragma unroll
    for (int o = 16; o; o >>= 1) m = fmaxf(m, __shfl_xor_sync(0xFFFFFFFFu, m, o));
    float e = expf(s - m);
    float sum = e;
#pragma unroll
    for (int o = 16; o; o >>= 1) sum += __shfl_xor_sync(0xFFFFFFFFu, sum, o);
    float w = e / sum;

    float acc0 = 0.f, acc1 = 0.f, acc2 = 0.f, acc3 = 0.f;
#pragma unroll
    for (int j = 0; j < Kn; j++) {
        float wj = __shfl_sync(0xFFFFFFFFu, w, j);
        int   ij = __shfl_sync(0xFFFFFFFFu, idx, j);
        const float* vp = vmat + (size_t)ij * Dn + h * HDn;
        acc0 = fmaf(wj, vp[lane],      acc0);
        acc1 = fmaf(wj, vp[lane + 32], acc1);
        acc2 = fmaf(wj, vp[lane + 64], acc2);
        acc3 = fmaf(wj, vp[lane + 96], acc3);
    }
    const size_t opofs = (size_t)t * Dn + h * HDn;
    {
        bf16 h0 = __float2bfloat16(acc0);
        bf16 h1 = __float2bfloat16(acc1);
        bf16 h2 = __float2bfloat16(acc2);
        bf16 h3 = __float2bfloat16(acc3);
        aohi[opofs + lane]      = h0;
        aohi[opofs + lane + 32] = h1;
        aohi[opofs + lane + 64] = h2;
        aohi[opofs + lane + 96] = h3;
        aolo[opofs + lane]      = __float2bfloat16(acc0 - __bfloat162float(h0));
        aolo[opofs + lane + 32] = __float2bfloat16(acc1 - __bfloat162float(h1));
        aolo[opofs + lane + 64] = __float2bfloat16(acc2 - __bfloat162float(h2));
        aolo[opofs + lane + 96] = __float2bfloat16(acc3 - __bfloat162float(h3));
    }
}

// ---------------------------------------------------------------------------
// Launcher
// ---------------------------------------------------------------------------
extern "C" void kernel_launch(void* const* d_in, const int* in_sizes, int n_in,
                              void* d_out, int out_size)
{
    const float* x    = (const float*)d_in[0];
    const float* Wqd  = (const float*)d_in[1];
    const float* Wqu  = (const float*)d_in[2];
    const float* Wqr  = (const float*)d_in[3];
    const float* Wkvd = (const float*)d_in[4];
    const float* Wku  = (const float*)d_in[5];
    const float* Wvu  = (const float*)d_in[6];
    const float* Wkr  = (const float*)d_in[7];
    const float* Wo   = (const float*)d_in[8];
    const int*   topk = (const int*)  d_in[9];
    float* out = (float*)d_out;

    float *q, *qr, *k, *v, *kr, *krp;
    cudaGetSymbolAddress((void**)&q,   g_q);
    cudaGetSymbolAddress((void**)&qr,  g_qr);
    cudaGetSymbolAddress((void**)&k,   g_k);
    cudaGetSymbolAddress((void**)&v,   g_v);
    cudaGetSymbolAddress((void**)&kr,  g_kr);
    cudaGetSymbolAddress((void**)&krp, g_krp);

    bf16 *x_hi, *x_lo, *ql_hi, *ql_lo, *ckv_hi, *ckv_lo, *ao_hi, *ao_lo;
    cudaGetSymbolAddress((void**)&x_hi,   g_x_hi);
    cudaGetSymbolAddress((void**)&x_lo,   g_x_lo);
    cudaGetSymbolAddress((void**)&ql_hi,  g_ql_hi);
    cudaGetSymbolAddress((void**)&ql_lo,  g_ql_lo);
    cudaGetSymbolAddress((void**)&ckv_hi, g_ckv_hi);
    cudaGetSymbolAddress((void**)&ckv_lo, g_ckv_lo);
    cudaGetSymbolAddress((void**)&ao_hi,  g_ao_hi);
    cudaGetSymbolAddress((void**)&ao_lo,  g_ao_lo);

    bf16 *WqdT_hi, *WqdT_lo, *WkvdT_hi, *WkvdT_lo, *WquT_hi, *WquT_lo,
         *WqrT_hi, *WqrT_lo, *WkuT_hi, *WkuT_lo, *WvuT_hi, *WvuT_lo,
         *WkrT_hi, *WkrT_lo, *WoT_hi, *WoT_lo;
    cudaGetSymbolAddress((void**)&WqdT_hi,  g_WqdT_hi);
    cudaGetSymbolAddress((void**)&WqdT_lo,  g_WqdT_lo);
    cudaGetSymbolAddress((void**)&WkvdT_hi, g_WkvdT_hi);
    cudaGetSymbolAddress((void**)&WkvdT_lo, g_WkvdT_lo);
    cudaGetSymbolAddress((void**)&WquT_hi,  g_WquT_hi);
    cudaGetSymbolAddress((void**)&WquT_lo,  g_WquT_lo);
    cudaGetSymbolAddress((void**)&WqrT_hi,  g_WqrT_hi);
    cudaGetSymbolAddress((void**)&WqrT_lo,  g_WqrT_lo);
    cudaGetSymbolAddress((void**)&WkuT_hi,  g_WkuT_hi);
    cudaGetSymbolAddress((void**)&WkuT_lo,  g_WkuT_lo);
    cudaGetSymbolAddress((void**)&WvuT_hi,  g_WvuT_hi);
    cudaGetSymbolAddress((void**)&WvuT_lo,  g_WvuT_lo);
    cudaGetSymbolAddress((void**)&WkrT_hi,  g_WkrT_hi);
    cudaGetSymbolAddress((void**)&WkrT_lo,  g_WkrT_lo);
    cudaGetSymbolAddress((void**)&WoT_hi,   g_WoT_hi);
    cudaGetSymbolAddress((void**)&WoT_lo,   g_WoT_lo);

    cudaFuncSetAttribute(mm_down_kernel, cudaFuncAttributeMaxDynamicSharedMemorySize, SMEM_MM);
    cudaFuncSetAttribute(mm_up_kernel,   cudaFuncAttributeMaxDynamicSharedMemorySize, SMEM_MM);
    cudaFuncSetAttribute(mm_wo_kernel,   cudaFuncAttributeMaxDynamicSharedMemorySize, SMEM_MM);

    // 1) merged preprocessing
    prep_kernel<<<11904, 256>>>(x, Wqd, Wqu, Wqr, Wkvd, Wku, Wvu, Wkr, Wo,
                                x_hi, x_lo,
                                WqdT_hi, WqdT_lo, WkvdT_hi, WkvdT_lo,
                                WquT_hi, WquT_lo, WqrT_hi, WqrT_lo,
                                WkuT_hi, WkuT_lo, WvuT_hi, WvuT_lo,
                                WkrT_hi, WkrT_lo, WoT_hi, WoT_lo);

    // 2) down-projections + kr partials (merged, 384 CTAs @ occ2)
    mm_down_kernel<<<384, 256, SMEM_MM>>>(x_hi, x_lo,
                                          WqdT_hi, WqdT_lo, WkvdT_hi, WkvdT_lo,
                                          WkrT_hi, WkrT_lo,
                                          ql_hi, ql_lo, ckv_hi, ckv_lo, krp);

    // 3) up-projections (merged: q, qr, k, v; 1792 CTAs @ occ2)
    mm_up_kernel<<<1792, 256, SMEM_MM>>>(ql_hi, ql_lo, ckv_hi, ckv_lo,
                                         WquT_hi, WquT_lo, WqrT_hi, WqrT_lo,
                                         WkuT_hi, WkuT_lo, WvuT_hi, WvuT_lo,
                                         q, qr, k, v);

    // 4) merged rope
    rope_kernel<<<(Tn * Hn * 32 + Tn * 32 + 255) / 256, 256>>>(qr, krp, kr);

    // 5) sparse attention
    attn_kernel<<<(Tn * Hn * 32 + 255) / 256, 256>>>(q, qr, k, v, kr, topk, ao_hi, ao_lo);

    // 6) output projection (512 CTAs @ occ2)
    mm_wo_kernel<<<512, 256, SMEM_MM>>>(ao_hi, ao_lo, WoT_hi, WoT_lo, out);
}